// round 14
// baseline (speedup 1.0000x reference)
#include <cuda_runtime.h>
#include <cuda_fp16.h>

#define Nn 10000
#define Ee 160000
#define Cc 8
#define Bb 64
#define EPSv 1e-5f

// Scratch (device globals; allocation-free per harness rules)
__device__ __half g_xT16[Ee * Bb];     // x transposed+permuted, fp16
__device__ float  g_w1s[Ee * Cc];      // w1 permuted, fp32 (consecutive float pairs = ready FFMA2 operands)
__device__ __half g_h[Nn * Bb * Cc];   // LN+ELU activations, fp16, layout (N, B, C)
__device__ int    g_cnt[Nn];
__device__ int    g_cursor[Nn];
__device__ int    g_start[Nn + 1];

// ---------------- packed f32x2 helpers (SASS FFMA2: 2 fp32 FMAs / issue slot) ----------------

__device__ __forceinline__ unsigned long long pack2(float lo, float hi) {
    unsigned long long r;
    asm("mov.b64 %0, {%1, %2};" : "=l"(r) : "f"(lo), "f"(hi));
    return r;
}
__device__ __forceinline__ void unpack2(float& lo, float& hi, unsigned long long v) {
    asm("mov.b64 {%0, %1}, %2;" : "=f"(lo), "=f"(hi) : "l"(v));
}
__device__ __forceinline__ void fma2(unsigned long long& d,
                                     unsigned long long a, unsigned long long b) {
    asm("fma.rn.f32x2 %0, %1, %2, %3;" : "=l"(d) : "l"(a), "l"(b), "l"(d));
}

// ---------------- histogram ----------------

__global__ void hist_kernel(const int* __restrict__ dst) {
    int e = blockIdx.x * blockDim.x + threadIdx.x;
    if (e < Ee) atomicAdd(&g_cnt[dst[e]], 1);
}

// Single-block exclusive scan over N=10000 counts; also seeds g_cursor = g_start
__global__ void scan_kernel() {
    __shared__ int sh[1024];
    const int CH = (Nn + 1023) / 1024;  // 10
    int t = threadIdx.x;
    int base = t * CH;
    int loc[CH];
    int s = 0;
#pragma unroll
    for (int i = 0; i < CH; i++) {
        int v = (base + i < Nn) ? g_cnt[base + i] : 0;
        loc[i] = s;
        s += v;
    }
    sh[t] = s;
    __syncthreads();
    for (int off = 1; off < 1024; off <<= 1) {
        int v = (t >= off) ? sh[t - off] : 0;
        __syncthreads();
        if (t >= off) sh[t] += v;
        __syncthreads();
    }
    int prev = (t > 0) ? sh[t - 1] : 0;
#pragma unroll
    for (int i = 0; i < CH; i++)
        if (base + i < Nn) {
            int v = prev + loc[i];
            g_start[base + i] = v;
            g_cursor[base + i] = v;
        }
    if (t == 1023) g_start[Nn] = sh[1023];
}

// ---------------- Fused rank-assign + transpose + permute (R11 form; w fp32) ----------------

__global__ void transpose_sort_kernel(const float* __restrict__ x,
                                      const int* __restrict__ dst,
                                      const float* __restrict__ w1) {
    __shared__ float tile[32][65];   // [e_local][b]
    __shared__ int ranks[32];
    int e0 = blockIdx.x * 32;
    int t = threadIdx.x;             // 256

    if (t < 32) {
        int d = dst[e0 + t];
        ranks[t] = atomicAdd(&g_cursor[d], 1);
    }

    int tx = t & 31, ty = t >> 5;    // tx = e_local, ty = 0..7
#pragma unroll
    for (int i = 0; i < 64; i += 8)
        tile[tx][ty + i] = x[(ty + i) * Ee + e0 + tx];
    __syncthreads();

    int b = t & 63, r = t >> 6;      // r = 0..3
#pragma unroll
    for (int i = 0; i < 32; i += 4)
        g_xT16[ranks[r + i] * Bb + b] = __float2half_rn(tile[r + i][b]);

    // permute w1 (fp32): thread t handles element t of this block's 32x8 chunk
    int er = t >> 3, c = t & 7;
    g_w1s[ranks[er] * 8 + c] = w1[e0 * 8 + t];
}

// ---------------- Fused scatter + bias + LayerNorm + ELU ----------------
// 64 threads per node (lane = b); FFMA2 packs the CHANNEL dim:
// acc = 4 c-pair b64 regs, w fp32 pairs load directly as f32x2 operands
// (zero packing), x duplicated with ONE pack per edge.

__global__ void scatter_ln_kernel(const float* __restrict__ b1,
                                  const float* __restrict__ gamma,
                                  const float* __restrict__ beta) {
    int node = blockIdx.x * 4 + (threadIdx.x >> 6);
    int b    = threadIdx.x & 63;
    if (node >= Nn) return;

    unsigned long long acc[4];       // c-pairs: (0,1),(2,3),(4,5),(6,7)
#pragma unroll
    for (int j = 0; j < 4; j++) acc[j] = pack2(0.0f, 0.0f);

    int s  = g_start[node];
    int se = g_start[node + 1];
    int i  = s;

    for (; i + 4 <= se; i += 4) {
        // 4 independent xv half loads (64B per warp each; MLP=4)
        __half xh0 = g_xT16[(i + 0) * Bb + b];
        __half xh1 = g_xT16[(i + 1) * Bb + b];
        __half xh2 = g_xT16[(i + 2) * Bb + b];
        __half xh3 = g_xT16[(i + 3) * Bb + b];

#pragma unroll
        for (int k = 0; k < 4; k++) {
            float xf = __half2float(k == 0 ? xh0 : (k == 1 ? xh1 : (k == 2 ? xh2 : xh3)));
            unsigned long long xp = pack2(xf, xf);
            const ulonglong2* wrow =
                reinterpret_cast<const ulonglong2*>(g_w1s + (i + k) * 8);
            ulonglong2 w0 = wrow[0];   // (w0,w1),(w2,w3) as f32x2
            ulonglong2 w1v = wrow[1];  // (w4,w5),(w6,w7)
            fma2(acc[0], xp, w0.x);
            fma2(acc[1], xp, w0.y);
            fma2(acc[2], xp, w1v.x);
            fma2(acc[3], xp, w1v.y);
        }
    }
    for (; i < se; i++) {
        float xf = __half2float(g_xT16[i * Bb + b]);
        unsigned long long xp = pack2(xf, xf);
        const ulonglong2* wrow = reinterpret_cast<const ulonglong2*>(g_w1s + i * 8);
        ulonglong2 w0 = wrow[0];
        ulonglong2 w1v = wrow[1];
        fma2(acc[0], xp, w0.x);
        fma2(acc[1], xp, w0.y);
        fma2(acc[2], xp, w1v.x);
        fma2(acc[3], xp, w1v.y);
    }

    // unpack: a[c] in natural channel order
    float a[8];
    unpack2(a[0], a[1], acc[0]);
    unpack2(a[2], a[3], acc[1]);
    unpack2(a[4], a[5], acc[2]);
    unpack2(a[6], a[7], acc[3]);

    float4 c0 = *reinterpret_cast<const float4*>(b1 + node * 8);
    float4 c1 = *reinterpret_cast<const float4*>(b1 + node * 8 + 4);
    a[0] += c0.x; a[1] += c0.y; a[2] += c0.z; a[3] += c0.w;
    a[4] += c1.x; a[5] += c1.y; a[6] += c1.z; a[7] += c1.w;

    float mu = 0.0f;
#pragma unroll
    for (int j = 0; j < 8; j++) mu += a[j];
    mu *= 0.125f;
    float var = 0.0f;
#pragma unroll
    for (int j = 0; j < 8; j++) { float d = a[j] - mu; var = fmaf(d, d, var); }
    var *= 0.125f;
    float rr = rsqrtf(var + EPSv);

    float4 ga = *reinterpret_cast<const float4*>(gamma + node * 8);
    float4 gb = *reinterpret_cast<const float4*>(gamma + node * 8 + 4);
    float4 ba = *reinterpret_cast<const float4*>(beta  + node * 8);
    float4 bb = *reinterpret_cast<const float4*>(beta  + node * 8 + 4);
    float gv[8] = {ga.x, ga.y, ga.z, ga.w, gb.x, gb.y, gb.z, gb.w};
    float bv[8] = {ba.x, ba.y, ba.z, ba.w, bb.x, bb.y, bb.z, bb.w};

    float h[8];
#pragma unroll
    for (int j = 0; j < 8; j++) {
        float v = fmaf((a[j] - mu) * rr, gv[j], bv[j]);
        h[j] = (v > 0.0f) ? v : expm1f(v);        // ELU, alpha=1
    }

    __half2 p0 = __floats2half2_rn(h[0], h[1]);
    __half2 p1 = __floats2half2_rn(h[2], h[3]);
    __half2 p2 = __floats2half2_rn(h[4], h[5]);
    __half2 p3 = __floats2half2_rn(h[6], h[7]);
    uint4 packed;
    packed.x = *reinterpret_cast<unsigned int*>(&p0);
    packed.y = *reinterpret_cast<unsigned int*>(&p1);
    packed.z = *reinterpret_cast<unsigned int*>(&p2);
    packed.w = *reinterpret_cast<unsigned int*>(&p3);
    *reinterpret_cast<uint4*>(g_h + node * (Bb * Cc) + b * Cc) = packed;
}

// ---------------- Fused gather + transpose + residual via smem staging (R9 form) ----------------

#define GE 64  // edges per block

__global__ void gather_fused_kernel(const float* __restrict__ w3,
                                    const float* __restrict__ b3,
                                    const int* __restrict__ src,
                                    const float* __restrict__ x,
                                    float* __restrict__ out) {
    __shared__ float tile[Bb][GE + 1];
    int e0 = blockIdx.x * GE;
    int t = threadIdx.x;          // 256
    int b = t & 63;
    int g = t >> 6;               // 0..3

#pragma unroll 4
    for (int i = g; i < GE; i += 4) {
        int e = e0 + i;
        int sn = __ldg(src + e);                   // uniform within group
        uint4 raw = *reinterpret_cast<const uint4*>(g_h + sn * (Bb * Cc) + b * Cc);
        float2 f0 = __half22float2(*reinterpret_cast<__half2*>(&raw.x));
        float2 f1 = __half22float2(*reinterpret_cast<__half2*>(&raw.y));
        float2 f2 = __half22float2(*reinterpret_cast<__half2*>(&raw.z));
        float2 f3 = __half22float2(*reinterpret_cast<__half2*>(&raw.w));
        float4 wa = *reinterpret_cast<const float4*>(w3 + e * 8);
        float4 wb = *reinterpret_cast<const float4*>(w3 + e * 8 + 4);
        float sum = __ldg(b3 + e);
        sum = fmaf(f0.x, wa.x, sum);
        sum = fmaf(f0.y, wa.y, sum);
        sum = fmaf(f1.x, wa.z, sum);
        sum = fmaf(f1.y, wa.w, sum);
        sum = fmaf(f2.x, wb.x, sum);
        sum = fmaf(f2.y, wb.y, sum);
        sum = fmaf(f3.x, wb.z, sum);
        sum = fmaf(f3.y, wb.w, sum);
        tile[b][i] = sum;                          // stride-65: conflict-free
    }
    __syncthreads();

    int el = t & 63;
#pragma unroll
    for (int k = 0; k < 16; k++) {
        int b2 = (t >> 6) + k * 4;
        int idx = b2 * Ee + e0 + el;
        __stcs(&out[idx], tile[b2][el] + x[idx]);
    }
}

// ---------------- Launch ----------------

extern "C" void kernel_launch(void* const* d_in, const int* in_sizes, int n_in,
                              void* d_out, int out_size) {
    const float* x     = (const float*)d_in[0];   // (B,E)
    const float* w1    = (const float*)d_in[1];   // (E,C)
    const float* b1    = (const float*)d_in[2];   // (N,C)
    const float* gamma = (const float*)d_in[3];   // (N,C)
    const float* beta  = (const float*)d_in[4];   // (N,C)
    const float* w3    = (const float*)d_in[5];   // (E,C)
    const float* b3    = (const float*)d_in[6];   // (E,)
    const int* edge_src = (const int*)d_in[7];    // (E,)
    const int* edge_dst = (const int*)d_in[8];    // (E,)
    float* out = (float*)d_out;                   // (B,E)

    // Zero histogram
    void* cnt_ptr = nullptr;
    cudaGetSymbolAddress(&cnt_ptr, g_cnt);
    cudaMemsetAsync(cnt_ptr, 0, Nn * sizeof(int));

    hist_kernel<<<(Ee + 255) / 256, 256>>>(edge_dst);
    scan_kernel<<<1, 1024>>>();

    // Fused rank-assign + transpose + permute (fp16 xT, fp32 w)
    transpose_sort_kernel<<<Ee / 32, 256>>>(x, edge_dst, w1);

    // Fused scatter + LN + ELU (64 thr/node, channel-packed FFMA2)
    scatter_ln_kernel<<<(Nn + 3) / 4, 256>>>(b1, gamma, beta);

    // Fused gather + transpose + residual
    gather_fused_kernel<<<Ee / GE, 256>>>(w3, b3, edge_src, x, out);
}